// round 12
// baseline (speedup 1.0000x reference)
#include <cuda_runtime.h>
#include <cuda_pipeline_primitives.h>
#include <cstdint>
#include <math.h>

// Inputs (metadata order):
//   0: coords     float32 [100000,3]
//   1: pairs      int32   [3200000,2]
//   2: box        float32 [3,3]
//   3: c6         float32 [8,8]
//   4: b          float32 [8,8]
//   5: cutoff     float32 scalar
//   6: atom_types int32   [100000]
// Output: float32 [3200000]

#define N_TYPES   8
#define MAX_ATOMS 100000
#define THREADS_P 128
#define BLOCKS_PER_SM 7
#define NUM_SMS   148

__device__ float4 g_atoms[MAX_ATOMS];

__global__ void pack_atoms_kernel(const float* __restrict__ coords,
                                  const int* __restrict__ types,
                                  int n_atoms)
{
    int i = blockIdx.x * blockDim.x + threadIdx.x;
    if (i >= n_atoms) return;
    float4 v;
    v.x = coords[3*i + 0];
    v.y = coords[3*i + 1];
    v.z = coords[3*i + 2];
    v.w = __int_as_float(types[i]);
    g_atoms[i] = v;
}

// ---------------------------------------------------------------- numerics --

// ~1-ulp fp32 exp (Cody-Waite + degree-6 minimax). x in [-88, 0].
__device__ __forceinline__ float exp_accurate(float x)
{
    const float LOG2EF = 1.44269504088896341f;
    const float C1 = 0.693359375f;
    const float C2 = -2.12194440e-4f;
    float j = rintf(x * LOG2EF);
    float f = fmaf(-j, C1, x);
    f = fmaf(-j, C2, f);
    float z = f * f;
    float p = 1.9875691500e-4f;
    p = fmaf(p, f, 1.3981999507e-3f);
    p = fmaf(p, f, 8.3334519073e-3f);
    p = fmaf(p, f, 4.1665795894e-2f);
    p = fmaf(p, f, 1.6666665459e-1f);
    p = fmaf(p, f, 5.0000001201e-1f);
    p = fmaf(p, z, f);
    p = p + 1.0f;
    int e = (int)j;
    float s = __int_as_float((e + 127) << 23);
    return p * s;
}

// Per-pair energy, replicating the reference f32 expression graph bitwise.
__device__ __forceinline__ float pair_energy(
    const float4 a, const float4 b,
    const float* __restrict__ sh_box, const float* __restrict__ sh_inv,
    float cut, int diag,
    const float* __restrict__ sh_c6, const float* __restrict__ sh_b)
{
    float dx = __fsub_rn(b.x, a.x);
    float dy = __fsub_rn(b.y, a.y);
    float dz = __fsub_rn(b.z, a.z);

    if (diag) {
        // Bitwise-equal to full chain when off-diagonals are +0.
        float t0 = rintf(__fmul_rn(dx, sh_inv[0]));
        float t1 = rintf(__fmul_rn(dy, sh_inv[4]));
        float t2 = rintf(__fmul_rn(dz, sh_inv[8]));
        dx = __fsub_rn(dx, __fmul_rn(t0, sh_box[0]));
        dy = __fsub_rn(dy, __fmul_rn(t1, sh_box[4]));
        dz = __fsub_rn(dz, __fmul_rn(t2, sh_box[8]));
    } else {
        float t0 = __fadd_rn(__fadd_rn(__fmul_rn(dx, sh_inv[0]), __fmul_rn(dy, sh_inv[3])), __fmul_rn(dz, sh_inv[6]));
        float t1 = __fadd_rn(__fadd_rn(__fmul_rn(dx, sh_inv[1]), __fmul_rn(dy, sh_inv[4])), __fmul_rn(dz, sh_inv[7]));
        float t2 = __fadd_rn(__fadd_rn(__fmul_rn(dx, sh_inv[2]), __fmul_rn(dy, sh_inv[5])), __fmul_rn(dz, sh_inv[8]));
        t0 = rintf(t0); t1 = rintf(t1); t2 = rintf(t2);
        float c0 = __fadd_rn(__fadd_rn(__fmul_rn(t0, sh_box[0]), __fmul_rn(t1, sh_box[3])), __fmul_rn(t2, sh_box[6]));
        float c1 = __fadd_rn(__fadd_rn(__fmul_rn(t0, sh_box[1]), __fmul_rn(t1, sh_box[4])), __fmul_rn(t2, sh_box[7]));
        float c2 = __fadd_rn(__fadd_rn(__fmul_rn(t0, sh_box[2]), __fmul_rn(t1, sh_box[5])), __fmul_rn(t2, sh_box[8]));
        dx = __fsub_rn(dx, c0);
        dy = __fsub_rn(dy, c1);
        dz = __fsub_rn(dz, c2);
    }

    float r2 = __fadd_rn(__fadd_rn(__fmul_rn(dx, dx), __fmul_rn(dy, dy)), __fmul_rn(dz, dz));
    float r  = __fsqrt_rn(r2);

    if (!(r <= cut)) return 0.0f;

    int ti = __float_as_int(a.w);
    int tj = __float_as_int(b.w);
    float c6ij = sh_c6[ti * N_TYPES + tj];
    float bij  = sh_b [ti * N_TYPES + tj];

    float u = __fmul_rn(bij, r);

    // poly = 1 + u*(1 + u/2*(1 + u/3*(1 + u/4*(1 + u/5*(1 + u/6)))))
    float s = __fadd_rn(1.0f, __fdiv_rn(u, 6.0f));
    s = __fadd_rn(1.0f, __fmul_rn(__fdiv_rn(u, 5.0f), s));
    s = __fadd_rn(1.0f, __fmul_rn(__fmul_rn(u, 0.25f), s));
    s = __fadd_rn(1.0f, __fmul_rn(__fdiv_rn(u, 3.0f), s));
    s = __fadd_rn(1.0f, __fmul_rn(__fmul_rn(u, 0.5f), s));
    float poly = __fadd_rn(1.0f, __fmul_rn(u, s));

    float g = exp_accurate(-u);
    float f6 = __fsub_rn(1.0f, __fmul_rn(g, poly));

    float rr = __fmul_rn(r, r);
    float r6 = __fmul_rn(__fmul_rn(rr, rr), rr);
    return -__fdiv_rn(__fmul_rn(c6ij, f6), r6);
}

// Shared one-time setup: tables + GJ box inverse + diag detection.
__device__ __forceinline__ void setup_shared(
    float* sh_c6, float* sh_b, float* sh_box, float* sh_inv,
    float* sh_cut, int* sh_diag,
    const float* c6t, const float* bt, const float* box, const float* cutoffp,
    int tid)
{
    if (tid < N_TYPES * N_TYPES) {
        sh_c6[tid] = c6t[tid];
        sh_b[tid]  = bt[tid];
    }
    if (tid == 0) {
        float A[3][3], I[3][3];
        #pragma unroll
        for (int r = 0; r < 3; r++)
            #pragma unroll
            for (int c = 0; c < 3; c++) {
                A[r][c] = box[3*r + c];
                I[r][c] = (r == c) ? 1.0f : 0.0f;
                sh_box[3*r + c] = box[3*r + c];
            }
        #pragma unroll
        for (int col = 0; col < 3; col++) {
            int piv = col;
            float best = fabsf(A[col][col]);
            #pragma unroll
            for (int r = 0; r < 3; r++)
                if (r > col && fabsf(A[r][col]) > best) { best = fabsf(A[r][col]); piv = r; }
            if (piv != col) {
                #pragma unroll
                for (int c = 0; c < 3; c++) {
                    float t = A[col][c]; A[col][c] = A[piv][c]; A[piv][c] = t;
                    t = I[col][c]; I[col][c] = I[piv][c]; I[piv][c] = t;
                }
            }
            float pv = A[col][col];
            #pragma unroll
            for (int c = 0; c < 3; c++) {
                A[col][c] = __fdiv_rn(A[col][c], pv);
                I[col][c] = __fdiv_rn(I[col][c], pv);
            }
            #pragma unroll
            for (int r = 0; r < 3; r++)
                if (r != col) {
                    float fr = A[r][col];
                    #pragma unroll
                    for (int c = 0; c < 3; c++) {
                        A[r][c] = __fsub_rn(A[r][c], __fmul_rn(fr, A[col][c]));
                        I[r][c] = __fsub_rn(I[r][c], __fmul_rn(fr, I[col][c]));
                    }
                }
        }
        int diag = 1;
        #pragma unroll
        for (int r = 0; r < 3; r++)
            #pragma unroll
            for (int c = 0; c < 3; c++) {
                sh_inv[3*r + c] = I[r][c];
                if (r != c && (I[r][c] != 0.0f || sh_box[3*r + c] != 0.0f)) diag = 0;
            }
        *sh_diag = diag;
        *sh_cut  = cutoffp[0];
    }
}

// ------------------------------------------------------- pipelined cp.async --

// Dynamic smem layout: float4 stage[2][8][THREADS_P]
__device__ __forceinline__ float4* stage_slot(float4* base, int p, int k, int tid)
{
    return base + ((p * 8 + k) * THREADS_P + tid);
}

// Issue 8 async 16B gathers for quad q into stage p (this thread's slots).
__device__ __forceinline__ void issue_stage(float4* base, int p, int tid,
                                            const int4* __restrict__ pairs2,
                                            int q, int n_quads)
{
    if (q < n_quads) {
        int4 pA = __ldg(pairs2 + 2*q + 0);
        int4 pB = __ldg(pairs2 + 2*q + 1);
        __pipeline_memcpy_async(stage_slot(base, p, 0, tid), &g_atoms[pA.x], 16);
        __pipeline_memcpy_async(stage_slot(base, p, 1, tid), &g_atoms[pA.y], 16);
        __pipeline_memcpy_async(stage_slot(base, p, 2, tid), &g_atoms[pA.z], 16);
        __pipeline_memcpy_async(stage_slot(base, p, 3, tid), &g_atoms[pA.w], 16);
        __pipeline_memcpy_async(stage_slot(base, p, 4, tid), &g_atoms[pB.x], 16);
        __pipeline_memcpy_async(stage_slot(base, p, 5, tid), &g_atoms[pB.y], 16);
        __pipeline_memcpy_async(stage_slot(base, p, 6, tid), &g_atoms[pB.z], 16);
        __pipeline_memcpy_async(stage_slot(base, p, 7, tid), &g_atoms[pB.w], 16);
    }
    __pipeline_commit();   // empty group is legal when q out of range
}

__global__ __launch_bounds__(THREADS_P, BLOCKS_PER_SM)
void dispersion_pipe_kernel(
    const int4*  __restrict__ pairs2,
    const float* __restrict__ box,
    const float* __restrict__ c6t,
    const float* __restrict__ bt,
    const float* __restrict__ cutoffp,
    float4* __restrict__ out4,
    int n_quads)
{
    extern __shared__ float4 sh_stage[];   // [2][8][THREADS_P] = 32 KB
    __shared__ float sh_c6[N_TYPES * N_TYPES];
    __shared__ float sh_b[N_TYPES * N_TYPES];
    __shared__ float sh_box[9];
    __shared__ float sh_inv[9];
    __shared__ float sh_cut;
    __shared__ int   sh_diag;

    int tid = threadIdx.x;
    setup_shared(sh_c6, sh_b, sh_box, sh_inv, &sh_cut, &sh_diag,
                 c6t, bt, box, cutoffp, tid);
    __syncthreads();

    float cut = sh_cut;
    int   diag = sh_diag;

    int idx0   = blockIdx.x * THREADS_P + tid;
    int stride = gridDim.x * THREADS_P;
    int niter  = (n_quads + stride - 1) / stride;   // uniform across all threads

    // Prologue: stage 0 for iteration 0.
    issue_stage(sh_stage, 0, tid, pairs2, idx0, n_quads);

    int p = 0;
    for (int it = 0; it < niter; it++) {
        int q  = idx0 + it * stride;
        int qn = q + stride;

        // Issue next iteration's gathers into the other stage.
        issue_stage(sh_stage, p ^ 1, tid, pairs2,
                    (it + 1 < niter) ? qn : n_quads, n_quads);

        // Wait until only the just-issued group is outstanding -> stage p ready.
        __pipeline_wait_prior(1);

        if (q < n_quads) {
            float4 a0 = *stage_slot(sh_stage, p, 0, tid);
            float4 b0 = *stage_slot(sh_stage, p, 1, tid);
            float4 a1 = *stage_slot(sh_stage, p, 2, tid);
            float4 b1 = *stage_slot(sh_stage, p, 3, tid);
            float4 a2 = *stage_slot(sh_stage, p, 4, tid);
            float4 b2 = *stage_slot(sh_stage, p, 5, tid);
            float4 a3 = *stage_slot(sh_stage, p, 6, tid);
            float4 b3 = *stage_slot(sh_stage, p, 7, tid);

            float4 e;
            e.x = pair_energy(a0, b0, sh_box, sh_inv, cut, diag, sh_c6, sh_b);
            e.y = pair_energy(a1, b1, sh_box, sh_inv, cut, diag, sh_c6, sh_b);
            e.z = pair_energy(a2, b2, sh_box, sh_inv, cut, diag, sh_c6, sh_b);
            e.w = pair_energy(a3, b3, sh_box, sh_inv, cut, diag, sh_c6, sh_b);

            out4[q] = e;
        }
        p ^= 1;
    }
    __pipeline_wait_prior(0);
}

// Scalar tail for n_pairs % 4 leftover pairs (not hit for 3.2M).
__global__ void dispersion_tail_kernel(
    const int2* __restrict__ pairs,
    const float* __restrict__ box,
    const float* __restrict__ c6t,
    const float* __restrict__ bt,
    const float* __restrict__ cutoffp,
    float* __restrict__ out,
    int start, int n_pairs)
{
    __shared__ float sh_c6[N_TYPES * N_TYPES];
    __shared__ float sh_b[N_TYPES * N_TYPES];
    __shared__ float sh_box[9];
    __shared__ float sh_inv[9];
    __shared__ float sh_cut;
    __shared__ int   sh_diag;

    int tid = threadIdx.x;
    setup_shared(sh_c6, sh_b, sh_box, sh_inv, &sh_cut, &sh_diag,
                 c6t, bt, box, cutoffp, tid);
    __syncthreads();

    int i = start + blockIdx.x * blockDim.x + tid;
    if (i >= n_pairs) return;

    int2 p = __ldg(pairs + i);
    float4 a = __ldg(&g_atoms[p.x]);
    float4 b = __ldg(&g_atoms[p.y]);
    out[i] = pair_energy(a, b, sh_box, sh_inv, sh_cut, sh_diag, sh_c6, sh_b);
}

// ------------------------------------------------------------------- launch --

extern "C" void kernel_launch(void* const* d_in, const int* in_sizes, int n_in,
                              void* d_out, int out_size)
{
    const float* coords  = (const float*)d_in[0];
    const int4*  pairs2  = (const int4*)d_in[1];
    const float* box     = (const float*)d_in[2];
    const float* c6t     = (const float*)d_in[3];
    const float* bt      = (const float*)d_in[4];
    const float* cutoffp = (const float*)d_in[5];
    const int*   types   = (const int*)d_in[6];
    float*       out     = (float*)d_out;

    int n_atoms = in_sizes[0] / 3;
    int n_pairs = out_size;
    int n_quads = n_pairs / 4;

    pack_atoms_kernel<<<(n_atoms + 255) / 256, 256>>>(coords, types, n_atoms);

    size_t dyn = (size_t)2 * 8 * THREADS_P * sizeof(float4);   // 32768 B
    cudaFuncSetAttribute(dispersion_pipe_kernel,
                         cudaFuncAttributeMaxDynamicSharedMemorySize, (int)dyn);

    int blocks = NUM_SMS * BLOCKS_PER_SM;   // 1036
    int max_blocks = (n_quads + THREADS_P - 1) / THREADS_P;
    if (blocks > max_blocks) blocks = max_blocks > 0 ? max_blocks : 1;

    dispersion_pipe_kernel<<<blocks, THREADS_P, dyn>>>(
        pairs2, box, c6t, bt, cutoffp, (float4*)out, n_quads);

    if (n_pairs & 3) {
        dispersion_tail_kernel<<<1, 32>>>((const int2*)d_in[1], box, c6t, bt,
                                          cutoffp, out, n_quads * 4, n_pairs);
    }
}

// round 13
// speedup vs baseline: 1.1358x; 1.1358x over previous
#include <cuda_runtime.h>
#include <cuda_pipeline_primitives.h>
#include <cstdint>
#include <math.h>

// Inputs (metadata order):
//   0: coords     float32 [100000,3]
//   1: pairs      int32   [3200000,2]
//   2: box        float32 [3,3]
//   3: c6         float32 [8,8]
//   4: b          float32 [8,8]
//   5: cutoff     float32 scalar
//   6: atom_types int32   [100000]
// Output: float32 [3200000]

#define N_TYPES   8
#define MAX_ATOMS 100000
#define THREADS_P 256
#define BLOCKS_P  444           // 3 blocks/SM on 148 SMs

__device__ float4 g_atoms[MAX_ATOMS];

__global__ void pack_atoms_kernel(const float* __restrict__ coords,
                                  const int* __restrict__ types,
                                  int n_atoms)
{
    int i = blockIdx.x * blockDim.x + threadIdx.x;
    if (i >= n_atoms) return;
    float4 v;
    v.x = coords[3*i + 0];
    v.y = coords[3*i + 1];
    v.z = coords[3*i + 2];
    v.w = __int_as_float(types[i]);
    g_atoms[i] = v;
}

// ---------------------------------------------------------------- numerics --

// ~1-ulp fp32 exp (Cody-Waite + degree-6 minimax). x in [-88, 0].
__device__ __forceinline__ float exp_accurate(float x)
{
    const float LOG2EF = 1.44269504088896341f;
    const float C1 = 0.693359375f;
    const float C2 = -2.12194440e-4f;
    float j = rintf(x * LOG2EF);
    float f = fmaf(-j, C1, x);
    f = fmaf(-j, C2, f);
    float z = f * f;
    float p = 1.9875691500e-4f;
    p = fmaf(p, f, 1.3981999507e-3f);
    p = fmaf(p, f, 8.3334519073e-3f);
    p = fmaf(p, f, 4.1665795894e-2f);
    p = fmaf(p, f, 1.6666665459e-1f);
    p = fmaf(p, f, 5.0000001201e-1f);
    p = fmaf(p, z, f);
    p = p + 1.0f;
    int e = (int)j;
    float s = __int_as_float((e + 127) << 23);
    return p * s;
}

// Per-pair energy, replicating the reference f32 expression graph bitwise.
__device__ __forceinline__ float pair_energy(
    const float4 a, const float4 b,
    const float* __restrict__ sh_box, const float* __restrict__ sh_inv,
    float cut, int diag,
    const float* __restrict__ sh_c6, const float* __restrict__ sh_b)
{
    float dx = __fsub_rn(b.x, a.x);
    float dy = __fsub_rn(b.y, a.y);
    float dz = __fsub_rn(b.z, a.z);

    if (diag) {
        // Bitwise-equal to full chain when off-diagonals are +0.
        float t0 = rintf(__fmul_rn(dx, sh_inv[0]));
        float t1 = rintf(__fmul_rn(dy, sh_inv[4]));
        float t2 = rintf(__fmul_rn(dz, sh_inv[8]));
        dx = __fsub_rn(dx, __fmul_rn(t0, sh_box[0]));
        dy = __fsub_rn(dy, __fmul_rn(t1, sh_box[4]));
        dz = __fsub_rn(dz, __fmul_rn(t2, sh_box[8]));
    } else {
        float t0 = __fadd_rn(__fadd_rn(__fmul_rn(dx, sh_inv[0]), __fmul_rn(dy, sh_inv[3])), __fmul_rn(dz, sh_inv[6]));
        float t1 = __fadd_rn(__fadd_rn(__fmul_rn(dx, sh_inv[1]), __fmul_rn(dy, sh_inv[4])), __fmul_rn(dz, sh_inv[7]));
        float t2 = __fadd_rn(__fadd_rn(__fmul_rn(dx, sh_inv[2]), __fmul_rn(dy, sh_inv[5])), __fmul_rn(dz, sh_inv[8]));
        t0 = rintf(t0); t1 = rintf(t1); t2 = rintf(t2);
        float c0 = __fadd_rn(__fadd_rn(__fmul_rn(t0, sh_box[0]), __fmul_rn(t1, sh_box[3])), __fmul_rn(t2, sh_box[6]));
        float c1 = __fadd_rn(__fadd_rn(__fmul_rn(t0, sh_box[1]), __fmul_rn(t1, sh_box[4])), __fmul_rn(t2, sh_box[7]));
        float c2 = __fadd_rn(__fadd_rn(__fmul_rn(t0, sh_box[2]), __fmul_rn(t1, sh_box[5])), __fmul_rn(t2, sh_box[8]));
        dx = __fsub_rn(dx, c0);
        dy = __fsub_rn(dy, c1);
        dz = __fsub_rn(dz, c2);
    }

    float r2 = __fadd_rn(__fadd_rn(__fmul_rn(dx, dx), __fmul_rn(dy, dy)), __fmul_rn(dz, dz));
    float r  = __fsqrt_rn(r2);

    if (!(r <= cut)) return 0.0f;

    int ti = __float_as_int(a.w);
    int tj = __float_as_int(b.w);
    float c6ij = sh_c6[ti * N_TYPES + tj];
    float bij  = sh_b [ti * N_TYPES + tj];

    float u = __fmul_rn(bij, r);

    // poly = 1 + u*(1 + u/2*(1 + u/3*(1 + u/4*(1 + u/5*(1 + u/6)))))
    float s = __fadd_rn(1.0f, __fdiv_rn(u, 6.0f));
    s = __fadd_rn(1.0f, __fmul_rn(__fdiv_rn(u, 5.0f), s));
    s = __fadd_rn(1.0f, __fmul_rn(__fmul_rn(u, 0.25f), s));
    s = __fadd_rn(1.0f, __fmul_rn(__fdiv_rn(u, 3.0f), s));
    s = __fadd_rn(1.0f, __fmul_rn(__fmul_rn(u, 0.5f), s));
    float poly = __fadd_rn(1.0f, __fmul_rn(u, s));

    float g = exp_accurate(-u);
    float f6 = __fsub_rn(1.0f, __fmul_rn(g, poly));

    float rr = __fmul_rn(r, r);
    float r6 = __fmul_rn(__fmul_rn(rr, rr), rr);
    return -__fdiv_rn(__fmul_rn(c6ij, f6), r6);
}

// Shared one-time setup: tables + GJ box inverse + diag detection.
__device__ __forceinline__ void setup_shared(
    float* sh_c6, float* sh_b, float* sh_box, float* sh_inv,
    float* sh_cut, int* sh_diag,
    const float* c6t, const float* bt, const float* box, const float* cutoffp,
    int tid)
{
    if (tid < N_TYPES * N_TYPES) {
        sh_c6[tid] = c6t[tid];
        sh_b[tid]  = bt[tid];
    }
    if (tid == 0) {
        float A[3][3], I[3][3];
        #pragma unroll
        for (int r = 0; r < 3; r++)
            #pragma unroll
            for (int c = 0; c < 3; c++) {
                A[r][c] = box[3*r + c];
                I[r][c] = (r == c) ? 1.0f : 0.0f;
                sh_box[3*r + c] = box[3*r + c];
            }
        #pragma unroll
        for (int col = 0; col < 3; col++) {
            int piv = col;
            float best = fabsf(A[col][col]);
            #pragma unroll
            for (int r = 0; r < 3; r++)
                if (r > col && fabsf(A[r][col]) > best) { best = fabsf(A[r][col]); piv = r; }
            if (piv != col) {
                #pragma unroll
                for (int c = 0; c < 3; c++) {
                    float t = A[col][c]; A[col][c] = A[piv][c]; A[piv][c] = t;
                    t = I[col][c]; I[col][c] = I[piv][c]; I[piv][c] = t;
                }
            }
            float pv = A[col][col];
            #pragma unroll
            for (int c = 0; c < 3; c++) {
                A[col][c] = __fdiv_rn(A[col][c], pv);
                I[col][c] = __fdiv_rn(I[col][c], pv);
            }
            #pragma unroll
            for (int r = 0; r < 3; r++)
                if (r != col) {
                    float fr = A[r][col];
                    #pragma unroll
                    for (int c = 0; c < 3; c++) {
                        A[r][c] = __fsub_rn(A[r][c], __fmul_rn(fr, A[col][c]));
                        I[r][c] = __fsub_rn(I[r][c], __fmul_rn(fr, I[col][c]));
                    }
                }
        }
        int diag = 1;
        #pragma unroll
        for (int r = 0; r < 3; r++)
            #pragma unroll
            for (int c = 0; c < 3; c++) {
                sh_inv[3*r + c] = I[r][c];
                if (r != c && (I[r][c] != 0.0f || sh_box[3*r + c] != 0.0f)) diag = 0;
            }
        *sh_diag = diag;
        *sh_cut  = cutoffp[0];
    }
}

// ------------------------------------------------------- pipelined cp.async --

// Dynamic smem layout: float4 stage[2][8][THREADS_P]
__device__ __forceinline__ float4* stage_slot(float4* base, int p, int k, int tid)
{
    return base + ((p * 8 + k) * THREADS_P + tid);
}

// Issue 8 async 16B gathers for quad q into stage p (this thread's slots).
__device__ __forceinline__ void issue_stage(float4* base, int p, int tid,
                                            const int4* __restrict__ pairs2,
                                            int q, int n_quads)
{
    if (q < n_quads) {
        int4 pA = __ldg(pairs2 + 2*q + 0);
        int4 pB = __ldg(pairs2 + 2*q + 1);
        __pipeline_memcpy_async(stage_slot(base, p, 0, tid), &g_atoms[pA.x], 16);
        __pipeline_memcpy_async(stage_slot(base, p, 1, tid), &g_atoms[pA.y], 16);
        __pipeline_memcpy_async(stage_slot(base, p, 2, tid), &g_atoms[pA.z], 16);
        __pipeline_memcpy_async(stage_slot(base, p, 3, tid), &g_atoms[pA.w], 16);
        __pipeline_memcpy_async(stage_slot(base, p, 4, tid), &g_atoms[pB.x], 16);
        __pipeline_memcpy_async(stage_slot(base, p, 5, tid), &g_atoms[pB.y], 16);
        __pipeline_memcpy_async(stage_slot(base, p, 6, tid), &g_atoms[pB.z], 16);
        __pipeline_memcpy_async(stage_slot(base, p, 7, tid), &g_atoms[pB.w], 16);
    }
    __pipeline_commit();   // empty group is legal when q out of range
}

__global__ __launch_bounds__(THREADS_P, 3)
void dispersion_hybrid_kernel(
    const int4*  __restrict__ pairs2,    // region A viewed as quads
    const int2*  __restrict__ pairs1,    // full pair array (region B singles)
    const float* __restrict__ box,
    const float* __restrict__ c6t,
    const float* __restrict__ bt,
    const float* __restrict__ cutoffp,
    float4* __restrict__ out4,
    float*  __restrict__ out,
    int n_quadsA,                        // region A quad count
    int baseB,                           // first pair index of region B
    int nB)                              // region B pair count
{
    extern __shared__ float4 sh_stage[];   // [2][8][THREADS_P] = 64 KB
    __shared__ float sh_c6[N_TYPES * N_TYPES];
    __shared__ float sh_b[N_TYPES * N_TYPES];
    __shared__ float sh_box[9];
    __shared__ float sh_inv[9];
    __shared__ float sh_cut;
    __shared__ int   sh_diag;

    int tid = threadIdx.x;
    setup_shared(sh_c6, sh_b, sh_box, sh_inv, &sh_cut, &sh_diag,
                 c6t, bt, box, cutoffp, tid);
    __syncthreads();

    float cut = sh_cut;
    int   diag = sh_diag;

    int idx0   = blockIdx.x * THREADS_P + tid;
    int stride = gridDim.x * THREADS_P;

    int niterA = (n_quadsA + stride - 1) / stride;
    int niterB = (nB + stride - 1) / stride;
    int niter  = niterA > niterB ? niterA : niterB;

    // Prologue: stage 0 for quad iteration 0.
    issue_stage(sh_stage, 0, tid, pairs2, idx0 < n_quadsA ? idx0 : n_quadsA,
                n_quadsA);

    // Prologue: register-buffered LDG for single-pair iteration 0.
    int  s_cur = idx0;
    bool bv_cur = (s_cur < nB);
    float4 sa_cur, sb_cur;
    if (bv_cur) {
        int2 p = __ldg(pairs1 + baseB + s_cur);
        sa_cur = __ldg(&g_atoms[p.x]);
        sb_cur = __ldg(&g_atoms[p.y]);
    }

    int ph = 0;
    for (int it = 0; it < niter; it++) {
        int q = idx0 + it * stride;

        // Issue next quad's gathers into the other stage.
        int qn = (it + 1 < niter) ? q + stride : n_quadsA;
        issue_stage(sh_stage, ph ^ 1, tid, pairs2, qn, n_quadsA);

        // Issue next single's register gathers (double-buffered).
        int  s_nxt = idx0 + (it + 1) * stride;
        bool bv_nxt = (it + 1 < niter) && (s_nxt < nB);
        float4 sa_nxt, sb_nxt;
        if (bv_nxt) {
            int2 p = __ldg(pairs1 + baseB + s_nxt);
            sa_nxt = __ldg(&g_atoms[p.x]);
            sb_nxt = __ldg(&g_atoms[p.y]);
        }

        // Stage ph is ready once only the just-issued group is outstanding.
        __pipeline_wait_prior(1);

        if (q < n_quadsA) {
            float4 a0 = *stage_slot(sh_stage, ph, 0, tid);
            float4 b0 = *stage_slot(sh_stage, ph, 1, tid);
            float4 a1 = *stage_slot(sh_stage, ph, 2, tid);
            float4 b1 = *stage_slot(sh_stage, ph, 3, tid);
            float4 a2 = *stage_slot(sh_stage, ph, 4, tid);
            float4 b2 = *stage_slot(sh_stage, ph, 5, tid);
            float4 a3 = *stage_slot(sh_stage, ph, 6, tid);
            float4 b3 = *stage_slot(sh_stage, ph, 7, tid);

            float4 e;
            e.x = pair_energy(a0, b0, sh_box, sh_inv, cut, diag, sh_c6, sh_b);
            e.y = pair_energy(a1, b1, sh_box, sh_inv, cut, diag, sh_c6, sh_b);
            e.z = pair_energy(a2, b2, sh_box, sh_inv, cut, diag, sh_c6, sh_b);
            e.w = pair_energy(a3, b3, sh_box, sh_inv, cut, diag, sh_c6, sh_b);

            out4[q] = e;
        }

        if (bv_cur) {
            out[baseB + s_cur] =
                pair_energy(sa_cur, sb_cur, sh_box, sh_inv, cut, diag,
                            sh_c6, sh_b);
        }

        s_cur  = s_nxt;
        bv_cur = bv_nxt;
        sa_cur = sa_nxt;
        sb_cur = sb_nxt;
        ph ^= 1;
    }
    __pipeline_wait_prior(0);
}

// ------------------------------------------------------------------- launch --

extern "C" void kernel_launch(void* const* d_in, const int* in_sizes, int n_in,
                              void* d_out, int out_size)
{
    const float* coords  = (const float*)d_in[0];
    const int4*  pairs2  = (const int4*)d_in[1];
    const int2*  pairs1  = (const int2*)d_in[1];
    const float* box     = (const float*)d_in[2];
    const float* c6t     = (const float*)d_in[3];
    const float* bt      = (const float*)d_in[4];
    const float* cutoffp = (const float*)d_in[5];
    const int*   types   = (const int*)d_in[6];
    float*       out     = (float*)d_out;

    int n_atoms = in_sizes[0] / 3;
    int n_pairs = out_size;

    // Region split: ~4/5 of pairs as pipeline quads, rest (incl. tail) singles.
    int nB_target = n_pairs / 5;
    int n_pairsA  = (n_pairs - nB_target) & ~3;   // multiple of 4
    int n_quadsA  = n_pairsA / 4;
    int baseB     = n_pairsA;
    int nB        = n_pairs - n_pairsA;

    pack_atoms_kernel<<<(n_atoms + 255) / 256, 256>>>(coords, types, n_atoms);

    size_t dyn = (size_t)2 * 8 * THREADS_P * sizeof(float4);   // 65536 B
    cudaFuncSetAttribute(dispersion_hybrid_kernel,
                         cudaFuncAttributeMaxDynamicSharedMemorySize, (int)dyn);

    int blocks = BLOCKS_P;
    dispersion_hybrid_kernel<<<blocks, THREADS_P, dyn>>>(
        pairs2, pairs1, box, c6t, bt, cutoffp,
        (float4*)out, out, n_quadsA, baseB, nB);
}

// round 14
// speedup vs baseline: 1.2679x; 1.1163x over previous
#include <cuda_runtime.h>
#include <cuda_pipeline_primitives.h>
#include <cstdint>
#include <math.h>

// Inputs (metadata order):
//   0: coords     float32 [100000,3]
//   1: pairs      int32   [3200000,2]
//   2: box        float32 [3,3]
//   3: c6         float32 [8,8]
//   4: b          float32 [8,8]
//   5: cutoff     float32 scalar
//   6: atom_types int32   [100000]
// Output: float32 [3200000]

#define N_TYPES   8
#define MAX_ATOMS 100000
#define THREADS_P 256
#define BLOCKS_PER_SM 4
#define NUM_SMS   148

__device__ float4 g_atoms[MAX_ATOMS];

__global__ void pack_atoms_kernel(const float* __restrict__ coords,
                                  const int* __restrict__ types,
                                  int n_atoms)
{
    int i = blockIdx.x * blockDim.x + threadIdx.x;
    if (i >= n_atoms) return;
    float4 v;
    v.x = coords[3*i + 0];
    v.y = coords[3*i + 1];
    v.z = coords[3*i + 2];
    v.w = __int_as_float(types[i]);
    g_atoms[i] = v;
}

// ---------------------------------------------------------------- numerics --

// ~1-ulp fp32 exp (Cody-Waite + degree-6 minimax). x in [-88, 0].
__device__ __forceinline__ float exp_accurate(float x)
{
    const float LOG2EF = 1.44269504088896341f;
    const float C1 = 0.693359375f;
    const float C2 = -2.12194440e-4f;
    float j = rintf(x * LOG2EF);
    float f = fmaf(-j, C1, x);
    f = fmaf(-j, C2, f);
    float z = f * f;
    float p = 1.9875691500e-4f;
    p = fmaf(p, f, 1.3981999507e-3f);
    p = fmaf(p, f, 8.3334519073e-3f);
    p = fmaf(p, f, 4.1665795894e-2f);
    p = fmaf(p, f, 1.6666665459e-1f);
    p = fmaf(p, f, 5.0000001201e-1f);
    p = fmaf(p, z, f);
    p = p + 1.0f;
    int e = (int)j;
    float s = __int_as_float((e + 127) << 23);
    return p * s;
}

// Per-pair energy, replicating the reference f32 expression graph bitwise.
__device__ __forceinline__ float pair_energy(
    const float4 a, const float4 b,
    const float* __restrict__ sh_box, const float* __restrict__ sh_inv,
    float cut, int diag,
    const float* __restrict__ sh_c6, const float* __restrict__ sh_b)
{
    float dx = __fsub_rn(b.x, a.x);
    float dy = __fsub_rn(b.y, a.y);
    float dz = __fsub_rn(b.z, a.z);

    if (diag) {
        // Bitwise-equal to full chain when off-diagonals are +0.
        float t0 = rintf(__fmul_rn(dx, sh_inv[0]));
        float t1 = rintf(__fmul_rn(dy, sh_inv[4]));
        float t2 = rintf(__fmul_rn(dz, sh_inv[8]));
        dx = __fsub_rn(dx, __fmul_rn(t0, sh_box[0]));
        dy = __fsub_rn(dy, __fmul_rn(t1, sh_box[4]));
        dz = __fsub_rn(dz, __fmul_rn(t2, sh_box[8]));
    } else {
        float t0 = __fadd_rn(__fadd_rn(__fmul_rn(dx, sh_inv[0]), __fmul_rn(dy, sh_inv[3])), __fmul_rn(dz, sh_inv[6]));
        float t1 = __fadd_rn(__fadd_rn(__fmul_rn(dx, sh_inv[1]), __fmul_rn(dy, sh_inv[4])), __fmul_rn(dz, sh_inv[7]));
        float t2 = __fadd_rn(__fadd_rn(__fmul_rn(dx, sh_inv[2]), __fmul_rn(dy, sh_inv[5])), __fmul_rn(dz, sh_inv[8]));
        t0 = rintf(t0); t1 = rintf(t1); t2 = rintf(t2);
        float c0 = __fadd_rn(__fadd_rn(__fmul_rn(t0, sh_box[0]), __fmul_rn(t1, sh_box[3])), __fmul_rn(t2, sh_box[6]));
        float c1 = __fadd_rn(__fadd_rn(__fmul_rn(t0, sh_box[1]), __fmul_rn(t1, sh_box[4])), __fmul_rn(t2, sh_box[7]));
        float c2 = __fadd_rn(__fadd_rn(__fmul_rn(t0, sh_box[2]), __fmul_rn(t1, sh_box[5])), __fmul_rn(t2, sh_box[8]));
        dx = __fsub_rn(dx, c0);
        dy = __fsub_rn(dy, c1);
        dz = __fsub_rn(dz, c2);
    }

    float r2 = __fadd_rn(__fadd_rn(__fmul_rn(dx, dx), __fmul_rn(dy, dy)), __fmul_rn(dz, dz));
    float r  = __fsqrt_rn(r2);

    if (!(r <= cut)) return 0.0f;

    int ti = __float_as_int(a.w);
    int tj = __float_as_int(b.w);
    float c6ij = sh_c6[ti * N_TYPES + tj];
    float bij  = sh_b [ti * N_TYPES + tj];

    float u = __fmul_rn(bij, r);

    // poly = 1 + u*(1 + u/2*(1 + u/3*(1 + u/4*(1 + u/5*(1 + u/6)))))
    float s = __fadd_rn(1.0f, __fdiv_rn(u, 6.0f));
    s = __fadd_rn(1.0f, __fmul_rn(__fdiv_rn(u, 5.0f), s));
    s = __fadd_rn(1.0f, __fmul_rn(__fmul_rn(u, 0.25f), s));
    s = __fadd_rn(1.0f, __fmul_rn(__fdiv_rn(u, 3.0f), s));
    s = __fadd_rn(1.0f, __fmul_rn(__fmul_rn(u, 0.5f), s));
    float poly = __fadd_rn(1.0f, __fmul_rn(u, s));

    float g = exp_accurate(-u);
    float f6 = __fsub_rn(1.0f, __fmul_rn(g, poly));

    float rr = __fmul_rn(r, r);
    float r6 = __fmul_rn(__fmul_rn(rr, rr), rr);
    return -__fdiv_rn(__fmul_rn(c6ij, f6), r6);
}

// Shared one-time setup: tables + GJ box inverse + diag detection.
__device__ __forceinline__ void setup_shared(
    float* sh_c6, float* sh_b, float* sh_box, float* sh_inv,
    float* sh_cut, int* sh_diag,
    const float* c6t, const float* bt, const float* box, const float* cutoffp,
    int tid)
{
    if (tid < N_TYPES * N_TYPES) {
        sh_c6[tid] = c6t[tid];
        sh_b[tid]  = bt[tid];
    }
    if (tid == 0) {
        float A[3][3], I[3][3];
        #pragma unroll
        for (int r = 0; r < 3; r++)
            #pragma unroll
            for (int c = 0; c < 3; c++) {
                A[r][c] = box[3*r + c];
                I[r][c] = (r == c) ? 1.0f : 0.0f;
                sh_box[3*r + c] = box[3*r + c];
            }
        #pragma unroll
        for (int col = 0; col < 3; col++) {
            int piv = col;
            float best = fabsf(A[col][col]);
            #pragma unroll
            for (int r = 0; r < 3; r++)
                if (r > col && fabsf(A[r][col]) > best) { best = fabsf(A[r][col]); piv = r; }
            if (piv != col) {
                #pragma unroll
                for (int c = 0; c < 3; c++) {
                    float t = A[col][c]; A[col][c] = A[piv][c]; A[piv][c] = t;
                    t = I[col][c]; I[col][c] = I[piv][c]; I[piv][c] = t;
                }
            }
            float pv = A[col][col];
            #pragma unroll
            for (int c = 0; c < 3; c++) {
                A[col][c] = __fdiv_rn(A[col][c], pv);
                I[col][c] = __fdiv_rn(I[col][c], pv);
            }
            #pragma unroll
            for (int r = 0; r < 3; r++)
                if (r != col) {
                    float fr = A[r][col];
                    #pragma unroll
                    for (int c = 0; c < 3; c++) {
                        A[r][c] = __fsub_rn(A[r][c], __fmul_rn(fr, A[col][c]));
                        I[r][c] = __fsub_rn(I[r][c], __fmul_rn(fr, I[col][c]));
                    }
                }
        }
        int diag = 1;
        #pragma unroll
        for (int r = 0; r < 3; r++)
            #pragma unroll
            for (int c = 0; c < 3; c++) {
                sh_inv[3*r + c] = I[r][c];
                if (r != c && (I[r][c] != 0.0f || sh_box[3*r + c] != 0.0f)) diag = 0;
            }
        *sh_diag = diag;
        *sh_cut  = cutoffp[0];
    }
}

// ------------------------------------------------------- pipelined cp.async --

// Dynamic smem layout: float4 stage[2][4][THREADS_P]  (2 pairs per thread/iter)
__device__ __forceinline__ float4* stage_slot(float4* base, int p, int k, int tid)
{
    return base + ((p * 4 + k) * THREADS_P + tid);
}

// Issue 4 async 16B gathers (2 pairs) for duo index d into stage p.
__device__ __forceinline__ void issue_stage(float4* base, int p, int tid,
                                            const int4* __restrict__ pairs2,
                                            int d, int n_duos)
{
    if (d < n_duos) {
        int4 pA = __ldg(pairs2 + d);   // two pairs
        __pipeline_memcpy_async(stage_slot(base, p, 0, tid), &g_atoms[pA.x], 16);
        __pipeline_memcpy_async(stage_slot(base, p, 1, tid), &g_atoms[pA.y], 16);
        __pipeline_memcpy_async(stage_slot(base, p, 2, tid), &g_atoms[pA.z], 16);
        __pipeline_memcpy_async(stage_slot(base, p, 3, tid), &g_atoms[pA.w], 16);
    }
    __pipeline_commit();   // empty group is legal when d out of range
}

__global__ __launch_bounds__(THREADS_P, BLOCKS_PER_SM)
void dispersion_pipe_kernel(
    const int4*  __restrict__ pairs2,   // 2 pairs per int4
    const float* __restrict__ box,
    const float* __restrict__ c6t,
    const float* __restrict__ bt,
    const float* __restrict__ cutoffp,
    float2* __restrict__ out2,
    int n_duos)                         // n_pairs / 2
{
    extern __shared__ float4 sh_stage[];   // [2][4][THREADS_P] = 32 KB
    __shared__ float sh_c6[N_TYPES * N_TYPES];
    __shared__ float sh_b[N_TYPES * N_TYPES];
    __shared__ float sh_box[9];
    __shared__ float sh_inv[9];
    __shared__ float sh_cut;
    __shared__ int   sh_diag;

    int tid = threadIdx.x;
    setup_shared(sh_c6, sh_b, sh_box, sh_inv, &sh_cut, &sh_diag,
                 c6t, bt, box, cutoffp, tid);
    __syncthreads();

    float cut = sh_cut;
    int   diag = sh_diag;

    int idx0   = blockIdx.x * THREADS_P + tid;
    int stride = gridDim.x * THREADS_P;
    int niter  = (n_duos + stride - 1) / stride;   // uniform across all threads

    // Prologue: stage 0 for iteration 0.
    issue_stage(sh_stage, 0, tid, pairs2, idx0, n_duos);

    int p = 0;
    for (int it = 0; it < niter; it++) {
        int d  = idx0 + it * stride;
        int dn = d + stride;

        // Issue next iteration's gathers into the other stage.
        issue_stage(sh_stage, p ^ 1, tid, pairs2,
                    (it + 1 < niter) ? dn : n_duos, n_duos);

        // Wait until only the just-issued group is outstanding -> stage p ready.
        __pipeline_wait_prior(1);

        if (d < n_duos) {
            float4 a0 = *stage_slot(sh_stage, p, 0, tid);
            float4 b0 = *stage_slot(sh_stage, p, 1, tid);
            float4 a1 = *stage_slot(sh_stage, p, 2, tid);
            float4 b1 = *stage_slot(sh_stage, p, 3, tid);

            float2 e;
            e.x = pair_energy(a0, b0, sh_box, sh_inv, cut, diag, sh_c6, sh_b);
            e.y = pair_energy(a1, b1, sh_box, sh_inv, cut, diag, sh_c6, sh_b);

            out2[d] = e;
        }
        p ^= 1;
    }
    __pipeline_wait_prior(0);
}

// Scalar tail for odd leftover pair (not hit for 3.2M).
__global__ void dispersion_tail_kernel(
    const int2* __restrict__ pairs,
    const float* __restrict__ box,
    const float* __restrict__ c6t,
    const float* __restrict__ bt,
    const float* __restrict__ cutoffp,
    float* __restrict__ out,
    int start, int n_pairs)
{
    __shared__ float sh_c6[N_TYPES * N_TYPES];
    __shared__ float sh_b[N_TYPES * N_TYPES];
    __shared__ float sh_box[9];
    __shared__ float sh_inv[9];
    __shared__ float sh_cut;
    __shared__ int   sh_diag;

    int tid = threadIdx.x;
    setup_shared(sh_c6, sh_b, sh_box, sh_inv, &sh_cut, &sh_diag,
                 c6t, bt, box, cutoffp, tid);
    __syncthreads();

    int i = start + blockIdx.x * blockDim.x + tid;
    if (i >= n_pairs) return;

    int2 p = __ldg(pairs + i);
    float4 a = __ldg(&g_atoms[p.x]);
    float4 b = __ldg(&g_atoms[p.y]);
    out[i] = pair_energy(a, b, sh_box, sh_inv, sh_cut, sh_diag, sh_c6, sh_b);
}

// ------------------------------------------------------------------- launch --

extern "C" void kernel_launch(void* const* d_in, const int* in_sizes, int n_in,
                              void* d_out, int out_size)
{
    const float* coords  = (const float*)d_in[0];
    const int4*  pairs2  = (const int4*)d_in[1];
    const float* box     = (const float*)d_in[2];
    const float* c6t     = (const float*)d_in[3];
    const float* bt      = (const float*)d_in[4];
    const float* cutoffp = (const float*)d_in[5];
    const int*   types   = (const int*)d_in[6];
    float*       out     = (float*)d_out;

    int n_atoms = in_sizes[0] / 3;
    int n_pairs = out_size;
    int n_duos  = n_pairs / 2;

    pack_atoms_kernel<<<(n_atoms + 255) / 256, 256>>>(coords, types, n_atoms);

    size_t dyn = (size_t)2 * 4 * THREADS_P * sizeof(float4);   // 32768 B
    cudaFuncSetAttribute(dispersion_pipe_kernel,
                         cudaFuncAttributeMaxDynamicSharedMemorySize, (int)dyn);

    int blocks = NUM_SMS * BLOCKS_PER_SM;   // 592
    int max_blocks = (n_duos + THREADS_P - 1) / THREADS_P;
    if (blocks > max_blocks) blocks = max_blocks > 0 ? max_blocks : 1;

    dispersion_pipe_kernel<<<blocks, THREADS_P, dyn>>>(
        pairs2, box, c6t, bt, cutoffp, (float2*)out, n_duos);

    if (n_pairs & 1) {
        dispersion_tail_kernel<<<1, 32>>>((const int2*)d_in[1], box, c6t, bt,
                                          cutoffp, out, n_duos * 2, n_pairs);
    }
}

// round 15
// speedup vs baseline: 1.2712x; 1.0026x over previous
#include <cuda_runtime.h>
#include <cuda_pipeline_primitives.h>
#include <cstdint>
#include <math.h>

// Inputs (metadata order):
//   0: coords     float32 [100000,3]
//   1: pairs      int32   [3200000,2]
//   2: box        float32 [3,3]
//   3: c6         float32 [8,8]
//   4: b          float32 [8,8]
//   5: cutoff     float32 scalar
//   6: atom_types int32   [100000]
// Output: float32 [3200000]

#define N_TYPES   8
#define MAX_ATOMS 100000
#define THREADS_P 256
#define BLOCKS_PER_SM 5
#define NUM_SMS   148

__device__ float4 g_atoms[MAX_ATOMS];

__global__ void pack_atoms_kernel(const float* __restrict__ coords,
                                  const int* __restrict__ types,
                                  int n_atoms)
{
    int i = blockIdx.x * blockDim.x + threadIdx.x;
    if (i >= n_atoms) return;
    float4 v;
    v.x = coords[3*i + 0];
    v.y = coords[3*i + 1];
    v.z = coords[3*i + 2];
    v.w = __int_as_float(types[i]);
    g_atoms[i] = v;
}

// ---------------------------------------------------------------- numerics --

// ~1-ulp fp32 exp (Cody-Waite + degree-6 minimax). x in [-88, 0].
__device__ __forceinline__ float exp_accurate(float x)
{
    const float LOG2EF = 1.44269504088896341f;
    const float C1 = 0.693359375f;
    const float C2 = -2.12194440e-4f;
    float j = rintf(x * LOG2EF);
    float f = fmaf(-j, C1, x);
    f = fmaf(-j, C2, f);
    float z = f * f;
    float p = 1.9875691500e-4f;
    p = fmaf(p, f, 1.3981999507e-3f);
    p = fmaf(p, f, 8.3334519073e-3f);
    p = fmaf(p, f, 4.1665795894e-2f);
    p = fmaf(p, f, 1.6666665459e-1f);
    p = fmaf(p, f, 5.0000001201e-1f);
    p = fmaf(p, z, f);
    p = p + 1.0f;
    int e = (int)j;
    float s = __int_as_float((e + 127) << 23);
    return p * s;
}

// Per-pair energy, replicating the reference f32 expression graph bitwise.
__device__ __forceinline__ float pair_energy(
    const float4 a, const float4 b,
    const float* __restrict__ sh_box, const float* __restrict__ sh_inv,
    float cut, int diag,
    const float* __restrict__ sh_c6, const float* __restrict__ sh_b)
{
    float dx = __fsub_rn(b.x, a.x);
    float dy = __fsub_rn(b.y, a.y);
    float dz = __fsub_rn(b.z, a.z);

    if (diag) {
        // Bitwise-equal to full chain when off-diagonals are +0.
        float t0 = rintf(__fmul_rn(dx, sh_inv[0]));
        float t1 = rintf(__fmul_rn(dy, sh_inv[4]));
        float t2 = rintf(__fmul_rn(dz, sh_inv[8]));
        dx = __fsub_rn(dx, __fmul_rn(t0, sh_box[0]));
        dy = __fsub_rn(dy, __fmul_rn(t1, sh_box[4]));
        dz = __fsub_rn(dz, __fmul_rn(t2, sh_box[8]));
    } else {
        float t0 = __fadd_rn(__fadd_rn(__fmul_rn(dx, sh_inv[0]), __fmul_rn(dy, sh_inv[3])), __fmul_rn(dz, sh_inv[6]));
        float t1 = __fadd_rn(__fadd_rn(__fmul_rn(dx, sh_inv[1]), __fmul_rn(dy, sh_inv[4])), __fmul_rn(dz, sh_inv[7]));
        float t2 = __fadd_rn(__fadd_rn(__fmul_rn(dx, sh_inv[2]), __fmul_rn(dy, sh_inv[5])), __fmul_rn(dz, sh_inv[8]));
        t0 = rintf(t0); t1 = rintf(t1); t2 = rintf(t2);
        float c0 = __fadd_rn(__fadd_rn(__fmul_rn(t0, sh_box[0]), __fmul_rn(t1, sh_box[3])), __fmul_rn(t2, sh_box[6]));
        float c1 = __fadd_rn(__fadd_rn(__fmul_rn(t0, sh_box[1]), __fmul_rn(t1, sh_box[4])), __fmul_rn(t2, sh_box[7]));
        float c2 = __fadd_rn(__fadd_rn(__fmul_rn(t0, sh_box[2]), __fmul_rn(t1, sh_box[5])), __fmul_rn(t2, sh_box[8]));
        dx = __fsub_rn(dx, c0);
        dy = __fsub_rn(dy, c1);
        dz = __fsub_rn(dz, c2);
    }

    float r2 = __fadd_rn(__fadd_rn(__fmul_rn(dx, dx), __fmul_rn(dy, dy)), __fmul_rn(dz, dz));
    float r  = __fsqrt_rn(r2);

    if (!(r <= cut)) return 0.0f;

    int ti = __float_as_int(a.w);
    int tj = __float_as_int(b.w);
    float c6ij = sh_c6[ti * N_TYPES + tj];
    float bij  = sh_b [ti * N_TYPES + tj];

    float u = __fmul_rn(bij, r);

    // poly = 1 + u*(1 + u/2*(1 + u/3*(1 + u/4*(1 + u/5*(1 + u/6)))))
    float s = __fadd_rn(1.0f, __fdiv_rn(u, 6.0f));
    s = __fadd_rn(1.0f, __fmul_rn(__fdiv_rn(u, 5.0f), s));
    s = __fadd_rn(1.0f, __fmul_rn(__fmul_rn(u, 0.25f), s));
    s = __fadd_rn(1.0f, __fmul_rn(__fdiv_rn(u, 3.0f), s));
    s = __fadd_rn(1.0f, __fmul_rn(__fmul_rn(u, 0.5f), s));
    float poly = __fadd_rn(1.0f, __fmul_rn(u, s));

    float g = exp_accurate(-u);
    float f6 = __fsub_rn(1.0f, __fmul_rn(g, poly));

    float rr = __fmul_rn(r, r);
    float r6 = __fmul_rn(__fmul_rn(rr, rr), rr);
    return -__fdiv_rn(__fmul_rn(c6ij, f6), r6);
}

// Shared one-time setup: tables + GJ box inverse + diag detection.
__device__ __forceinline__ void setup_shared(
    float* sh_c6, float* sh_b, float* sh_box, float* sh_inv,
    float* sh_cut, int* sh_diag,
    const float* c6t, const float* bt, const float* box, const float* cutoffp,
    int tid)
{
    if (tid < N_TYPES * N_TYPES) {
        sh_c6[tid] = c6t[tid];
        sh_b[tid]  = bt[tid];
    }
    if (tid == 0) {
        float A[3][3], I[3][3];
        #pragma unroll
        for (int r = 0; r < 3; r++)
            #pragma unroll
            for (int c = 0; c < 3; c++) {
                A[r][c] = box[3*r + c];
                I[r][c] = (r == c) ? 1.0f : 0.0f;
                sh_box[3*r + c] = box[3*r + c];
            }
        #pragma unroll
        for (int col = 0; col < 3; col++) {
            int piv = col;
            float best = fabsf(A[col][col]);
            #pragma unroll
            for (int r = 0; r < 3; r++)
                if (r > col && fabsf(A[r][col]) > best) { best = fabsf(A[r][col]); piv = r; }
            if (piv != col) {
                #pragma unroll
                for (int c = 0; c < 3; c++) {
                    float t = A[col][c]; A[col][c] = A[piv][c]; A[piv][c] = t;
                    t = I[col][c]; I[col][c] = I[piv][c]; I[piv][c] = t;
                }
            }
            float pv = A[col][col];
            #pragma unroll
            for (int c = 0; c < 3; c++) {
                A[col][c] = __fdiv_rn(A[col][c], pv);
                I[col][c] = __fdiv_rn(I[col][c], pv);
            }
            #pragma unroll
            for (int r = 0; r < 3; r++)
                if (r != col) {
                    float fr = A[r][col];
                    #pragma unroll
                    for (int c = 0; c < 3; c++) {
                        A[r][c] = __fsub_rn(A[r][c], __fmul_rn(fr, A[col][c]));
                        I[r][c] = __fsub_rn(I[r][c], __fmul_rn(fr, I[col][c]));
                    }
                }
        }
        int diag = 1;
        #pragma unroll
        for (int r = 0; r < 3; r++)
            #pragma unroll
            for (int c = 0; c < 3; c++) {
                sh_inv[3*r + c] = I[r][c];
                if (r != c && (I[r][c] != 0.0f || sh_box[3*r + c] != 0.0f)) diag = 0;
            }
        *sh_diag = diag;
        *sh_cut  = cutoffp[0];
    }
}

// ------------------------------------------------------- pipelined cp.async --

// Dynamic smem layout: float4 stage[2][4][THREADS_P]  (2 pairs per thread/iter)
__device__ __forceinline__ float4* stage_slot(float4* base, int p, int k, int tid)
{
    return base + ((p * 4 + k) * THREADS_P + tid);
}

// Issue 4 async 16B gathers (2 pairs) for duo index d into stage p.
__device__ __forceinline__ void issue_stage(float4* base, int p, int tid,
                                            const int4* __restrict__ pairs2,
                                            int d, int n_duos)
{
    if (d < n_duos) {
        int4 pA = __ldg(pairs2 + d);   // two pairs
        __pipeline_memcpy_async(stage_slot(base, p, 0, tid), &g_atoms[pA.x], 16);
        __pipeline_memcpy_async(stage_slot(base, p, 1, tid), &g_atoms[pA.y], 16);
        __pipeline_memcpy_async(stage_slot(base, p, 2, tid), &g_atoms[pA.z], 16);
        __pipeline_memcpy_async(stage_slot(base, p, 3, tid), &g_atoms[pA.w], 16);
    }
    __pipeline_commit();   // empty group is legal when d out of range
}

__global__ __launch_bounds__(THREADS_P, BLOCKS_PER_SM)
void dispersion_pipe_kernel(
    const int4*  __restrict__ pairs2,   // 2 pairs per int4
    const float* __restrict__ box,
    const float* __restrict__ c6t,
    const float* __restrict__ bt,
    const float* __restrict__ cutoffp,
    float2* __restrict__ out2,
    int n_duos)                         // n_pairs / 2
{
    extern __shared__ float4 sh_stage[];   // [2][4][THREADS_P] = 32 KB
    __shared__ float sh_c6[N_TYPES * N_TYPES];
    __shared__ float sh_b[N_TYPES * N_TYPES];
    __shared__ float sh_box[9];
    __shared__ float sh_inv[9];
    __shared__ float sh_cut;
    __shared__ int   sh_diag;

    int tid = threadIdx.x;
    setup_shared(sh_c6, sh_b, sh_box, sh_inv, &sh_cut, &sh_diag,
                 c6t, bt, box, cutoffp, tid);
    __syncthreads();

    float cut = sh_cut;
    int   diag = sh_diag;

    int idx0   = blockIdx.x * THREADS_P + tid;
    int stride = gridDim.x * THREADS_P;
    int niter  = (n_duos + stride - 1) / stride;   // uniform across all threads

    // Prologue: stage 0 for iteration 0.
    issue_stage(sh_stage, 0, tid, pairs2, idx0, n_duos);

    int p = 0;
    for (int it = 0; it < niter; it++) {
        int d  = idx0 + it * stride;
        int dn = d + stride;

        // Issue next iteration's gathers into the other stage.
        issue_stage(sh_stage, p ^ 1, tid, pairs2,
                    (it + 1 < niter) ? dn : n_duos, n_duos);

        // Wait until only the just-issued group is outstanding -> stage p ready.
        __pipeline_wait_prior(1);

        if (d < n_duos) {
            float4 a0 = *stage_slot(sh_stage, p, 0, tid);
            float4 b0 = *stage_slot(sh_stage, p, 1, tid);
            float4 a1 = *stage_slot(sh_stage, p, 2, tid);
            float4 b1 = *stage_slot(sh_stage, p, 3, tid);

            float2 e;
            e.x = pair_energy(a0, b0, sh_box, sh_inv, cut, diag, sh_c6, sh_b);
            e.y = pair_energy(a1, b1, sh_box, sh_inv, cut, diag, sh_c6, sh_b);

            out2[d] = e;
        }
        p ^= 1;
    }
    __pipeline_wait_prior(0);
}

// Scalar tail for odd leftover pair (not hit for 3.2M).
__global__ void dispersion_tail_kernel(
    const int2* __restrict__ pairs,
    const float* __restrict__ box,
    const float* __restrict__ c6t,
    const float* __restrict__ bt,
    const float* __restrict__ cutoffp,
    float* __restrict__ out,
    int start, int n_pairs)
{
    __shared__ float sh_c6[N_TYPES * N_TYPES];
    __shared__ float sh_b[N_TYPES * N_TYPES];
    __shared__ float sh_box[9];
    __shared__ float sh_inv[9];
    __shared__ float sh_cut;
    __shared__ int   sh_diag;

    int tid = threadIdx.x;
    setup_shared(sh_c6, sh_b, sh_box, sh_inv, &sh_cut, &sh_diag,
                 c6t, bt, box, cutoffp, tid);
    __syncthreads();

    int i = start + blockIdx.x * blockDim.x + tid;
    if (i >= n_pairs) return;

    int2 p = __ldg(pairs + i);
    float4 a = __ldg(&g_atoms[p.x]);
    float4 b = __ldg(&g_atoms[p.y]);
    out[i] = pair_energy(a, b, sh_box, sh_inv, sh_cut, sh_diag, sh_c6, sh_b);
}

// ------------------------------------------------------------------- launch --

extern "C" void kernel_launch(void* const* d_in, const int* in_sizes, int n_in,
                              void* d_out, int out_size)
{
    const float* coords  = (const float*)d_in[0];
    const int4*  pairs2  = (const int4*)d_in[1];
    const float* box     = (const float*)d_in[2];
    const float* c6t     = (const float*)d_in[3];
    const float* bt      = (const float*)d_in[4];
    const float* cutoffp = (const float*)d_in[5];
    const int*   types   = (const int*)d_in[6];
    float*       out     = (float*)d_out;

    int n_atoms = in_sizes[0] / 3;
    int n_pairs = out_size;
    int n_duos  = n_pairs / 2;

    pack_atoms_kernel<<<(n_atoms + 255) / 256, 256>>>(coords, types, n_atoms);

    size_t dyn = (size_t)2 * 4 * THREADS_P * sizeof(float4);   // 32768 B
    cudaFuncSetAttribute(dispersion_pipe_kernel,
                         cudaFuncAttributeMaxDynamicSharedMemorySize, (int)dyn);

    int blocks = NUM_SMS * BLOCKS_PER_SM;   // 740
    int max_blocks = (n_duos + THREADS_P - 1) / THREADS_P;
    if (blocks > max_blocks) blocks = max_blocks > 0 ? max_blocks : 1;

    dispersion_pipe_kernel<<<blocks, THREADS_P, dyn>>>(
        pairs2, box, c6t, bt, cutoffp, (float2*)out, n_duos);

    if (n_pairs & 1) {
        dispersion_tail_kernel<<<1, 32>>>((const int2*)d_in[1], box, c6t, bt,
                                          cutoffp, out, n_duos * 2, n_pairs);
    }
}